// round 1
// baseline (speedup 1.0000x reference)
#include <cuda_runtime.h>
#include <math.h>

#define NT 512
#define NFEAT 1024
#define NCAT 1536
#define NFUNC 32
#define MEMSZ 16384
#define SQRTNF 5.656854249492381f

// ---- output layout (float element offsets) ----
#define OUT_MEM    0
#define OUT_TMEM   8388608
#define OUT_FMEM   8404992
#define OUT_ARE    25182208
#define OUT_AIM    25198592
#define OUT_FREQ   25214976
#define OUT_RP     25215008
#define OUT_BIAS   26001440
#define OUT_FMEAN  26001952
#define OUT_AGRE   26002976
#define OUT_AGIM   26019360
#define OUT_FG     26035744
#define OUT_RPG    26035776

// ---- scratch ----
__device__ float g_u[32 * NCAT];        // [sample][1536]  (x - fmean | z_ - bias)
__device__ float g_zb[32 * NT];         // gathered targets
__device__ float g_zhat[16 * NT];
__device__ float g_G[16 * NT];          // dL/dr
__device__ float g_D[16 * NT];          // dL/dz_
__device__ float g_ctab[16 * NFUNC];
__device__ float g_stab[16 * NFUNC];
__device__ float g_twopit[32];
__device__ float g_dfrdfq[NFUNC];
__device__ float g_rpart[12 * 16 * NT];
__device__ float g_RzT[NT * NT];
__device__ float g_agre[NFUNC * NT];
__device__ float g_agim[NFUNC * NT];
__device__ float g_fg[NFUNC];
__device__ float g_rg[NCAT * NT];
__device__ float g_bias[NT];
__device__ float g_fmean[NFEAT];
__device__ float g_norms[3];            // sumsq: amp, freq, rp
__device__ float g_lr;

__device__ __forceinline__ float sgnf(float v) {
    return (v > 0.f) ? 1.f : ((v < 0.f) ? -1.f : 0.f);
}

// bias/fmean update + lr
__global__ void k_prep(const float* __restrict__ bias, const float* __restrict__ fmean,
                       const float* __restrict__ z, const float* __restrict__ x,
                       const int* __restrict__ dsp, float* __restrict__ out) {
    int tid = threadIdx.x;
    int ds = *dsp;
    float dsn = (float)(ds + 1);
    if (tid < NT) {
        float bv = (bias[tid] * dsn + z[tid]) / (dsn + 1.0f);
        g_bias[tid] = bv;
        out[OUT_BIAS + tid] = bv;
    }
    if (tid < NFEAT) {
        float fv = (fmean[tid] * dsn + x[tid]) / (dsn + 1.0f);
        g_fmean[tid] = fv;
        out[OUT_FMEAN + tid] = fv;
    }
    if (tid == 0) g_lr = (float)pow(0.977, (double)(ds + 1));
}

// t_memory -> float with row update
__global__ void k_tconv(const int* __restrict__ tmem, const int* __restrict__ tp,
                        const int* __restrict__ dsp, float* __restrict__ out) {
    int i = blockIdx.x * blockDim.x + threadIdx.x;
    if (i < MEMSZ) {
        int ds = *dsp;
        int v = (i == ds) ? *tp : tmem[i];
        out[OUT_TMEM + i] = (float)v;
    }
}

// overwrite updated rows of memory / feat_memory in out
__global__ void k_rows(const float* __restrict__ z, const float* __restrict__ x,
                       const int* __restrict__ dsp, float* __restrict__ out) {
    int tid = threadIdx.x;
    int ds = *dsp;
    if (tid < NT)    out[OUT_MEM + ds * NT + tid] = z[tid];
    if (tid < NFEAT) out[OUT_FMEM + ds * NFEAT + tid] = x[tid];
}

// gather all 32 samples: z_b, u-x-part, 2*pi*t
__global__ void k_gather(const int* __restrict__ ts, const float* __restrict__ memory,
                         const float* __restrict__ fmem, const int* __restrict__ tmem,
                         const float* __restrict__ z, const float* __restrict__ x,
                         const int* __restrict__ tp, const int* __restrict__ dsp) {
    int s = blockIdx.x;
    int tid = threadIdx.x;
    int ds = *dsp;
    int idx = ts[s];
    if (tid < NT)
        g_zb[s * NT + tid] = (idx == ds) ? z[tid] : memory[idx * NT + tid];
    float xv = (idx == ds) ? x[tid] : fmem[idx * NFEAT + tid];
    g_u[s * NCAT + tid] = xv - g_fmean[tid];
    if (tid == 0) {
        float tv = (idx == ds) ? (float)(*tp) : (float)tmem[idx];
        g_twopit[s] = 6.2831853071795864769f * tv;
    }
}

// evaluate z_hat, fill uz, trig tables; zero norm accumulators
__global__ void k_eval(int b, const float* __restrict__ cfreq, float* __restrict__ out) {
    __shared__ float sc[NFUNC], ss[NFUNC];
    int i = blockIdx.x;
    int tid = threadIdx.x;
    float tt = g_twopit[b * 16 + i];
    if (tid < NFUNC) {
        double fq = (double)out[OUT_FREQ + tid];
        double th = tanh(fq);
        double w = (double)cfreq[tid] + 2.0 * th;
        double sg = 1.0 / (1.0 + exp(-w));
        float fr = (float)(sg * 0.5);
        double ph = (double)(tt * fr);
        float cv = (float)cos(ph);
        float sv = (float)sin(ph);
        sc[tid] = cv; ss[tid] = sv;
        g_ctab[i * NFUNC + tid] = cv;
        g_stab[i * NFUNC + tid] = sv;
        if (i == 0)
            g_dfrdfq[tid] = (float)(0.5 * sg * (1.0 - sg) * 2.0 * (1.0 - th * th));
    }
    if (i == 0 && tid < 3) g_norms[tid] = 0.f;
    __syncthreads();
    const float* are = out + OUT_ARE;
    const float* aim = out + OUT_AIM;
    float acc = 0.f;
#pragma unroll
    for (int f = 0; f < NFUNC; f++)
        acc += sc[f] * are[f * NT + tid] - ss[f] * aim[f * NT + tid];
    float zh = acc / SQRTNF + g_bias[tid];
    g_zhat[i * NT + tid] = zh;
    g_u[(b * 16 + i) * NCAT + NFEAT + tid] = zh - g_bias[tid];
}

// partial r = u @ rp (split over j into 12 slices)
__global__ void k_r_part(int b, const float* __restrict__ out) {
    __shared__ float su[16][128];
    int t = blockIdx.x * 128 + threadIdx.x;
    int j0 = blockIdx.y * 128;
    for (int k = threadIdx.x; k < 16 * 128; k += 128) {
        int i = k >> 7, jj = k & 127;
        su[i][jj] = g_u[(b * 16 + i) * NCAT + j0 + jj];
    }
    __syncthreads();
    const float* rp = out + OUT_RP;
    float acc[16];
#pragma unroll
    for (int i = 0; i < 16; i++) acc[i] = 0.f;
    for (int jj = 0; jj < 128; jj++) {
        float rpv = rp[(j0 + jj) * NT + t];
#pragma unroll
        for (int i = 0; i < 16; i++) acc[i] += su[i][jj] * rpv;
    }
#pragma unroll
    for (int i = 0; i < 16; i++)
        g_rpart[(blockIdx.y * 16 + i) * NT + t] = acc[i];
}

// finish r, compute G and base D
__global__ void k_r_finish(int b) {
    int i = blockIdx.x;
    int t = threadIdx.x;
    int idx = i * NT + t;
    float r = 0.f;
#pragma unroll
    for (int s = 0; s < 12; s++) r += g_rpart[(s * 16 + i) * NT + t];
    float zh = g_zhat[idx];
    float zb = g_zb[(b * 16 + i) * NT + t];
    float ar = fabsf(r) + 1.0f;
    float z2 = zh + r / ar;
    g_G[idx] = (-0.03f / 16.0f) * sgnf(zb - z2) / (ar * ar);
    g_D[idx] = (-1.0f / 16.0f) * sgnf(zb - zh);
}

// transpose z-half of rp: RzT[t'][t] = rp[1024+t][t']
__global__ void k_transpose(const float* __restrict__ out) {
    __shared__ float tile[32][33];
    const float* rz = out + OUT_RP + NFEAT * NT;
    int x = blockIdx.x * 32 + threadIdx.x;
    int y = blockIdx.y * 32 + threadIdx.y;
    tile[threadIdx.y][threadIdx.x] = rz[y * NT + x];
    __syncthreads();
    int x2 = blockIdx.y * 32 + threadIdx.x;
    int y2 = blockIdx.x * 32 + threadIdx.y;
    g_RzT[y2 * NT + x2] = tile[threadIdx.x][threadIdx.y];
}

// D += G @ Rz^T   (backprop of res path into z_)
__global__ void k_backD() {
    __shared__ float sG[NT];
    int t = blockIdx.x * 128 + threadIdx.x;
    int i = blockIdx.y;
    for (int k = threadIdx.x; k < NT; k += 128) sG[k] = g_G[i * NT + k];
    __syncthreads();
    float acc = 0.f;
#pragma unroll 4
    for (int tp = 0; tp < NT; tp++) acc += sG[tp] * g_RzT[tp * NT + t];
    g_D[i * NT + t] += acc;
}

// amp + freq gradients
__global__ void k_ampgrad(int b, const float* __restrict__ out) {
    __shared__ float sh[NT];
    int f = blockIdx.x;
    int t = threadIdx.x;
    float are = out[OUT_ARE + f * NT + t];
    float aim = out[OUT_AIM + f * NT + t];
    float sre = 0.f, sim = 0.f, sf = 0.f;
#pragma unroll
    for (int i = 0; i < 16; i++) {
        float d = g_D[i * NT + t];
        float c = g_ctab[i * NFUNC + f];
        float s = g_stab[i * NFUNC + f];
        sre += d * c;
        sim -= d * s;
        sf += d * (-s * are - c * aim) * g_twopit[b * 16 + i];
    }
    float q = are * are + aim * aim;
    float aa = sqrtf(q);
    float reg = 0.01f / (2.0f * aa * sqrtf(aa));
    float agre = sre / SQRTNF + are * reg;
    float agim = sim / SQRTNF + aim * reg;
    g_agre[f * NT + t] = agre;
    g_agim[f * NT + t] = agim;

    sh[t] = sf;
    __syncthreads();
    for (int s2 = 256; s2 > 0; s2 >>= 1) {
        if (t < s2) sh[t] += sh[t + s2];
        __syncthreads();
    }
    if (t == 0) {
        float fg = (sh[0] / SQRTNF) * g_dfrdfq[f];
        g_fg[f] = fg;
        atomicAdd(&g_norms[1], fg * fg);
    }
    __syncthreads();
    sh[t] = agre * agre + agim * agim;
    __syncthreads();
    for (int s2 = 256; s2 > 0; s2 >>= 1) {
        if (t < s2) sh[t] += sh[t + s2];
        __syncthreads();
    }
    if (t == 0) atomicAdd(&g_norms[0], sh[0]);
}

// rg = u^T @ G
__global__ void k_rpgrad(int b) {
    __shared__ float sh[NT];
    int j = blockIdx.x;
    int t = threadIdx.x;
    float acc = 0.f;
#pragma unroll
    for (int i = 0; i < 16; i++)
        acc += g_u[(b * 16 + i) * NCAT + j] * g_G[i * NT + t];
    g_rg[j * NT + t] = acc;
    sh[t] = acc * acc;
    __syncthreads();
    for (int s = 256; s > 0; s >>= 1) {
        if (t < s) sh[t] += sh[t + s];
        __syncthreads();
    }
    if (t == 0) atomicAdd(&g_norms[2], sh[0]);
}

// momentum updates, in place in d_out
__global__ void k_update(float* __restrict__ out) {
    int idx = blockIdx.x * 256 + threadIdx.x;
    float lr = g_lr;
    if (idx < NCAT * NT) {
        float rn = sqrtf(g_norms[2]) + 1.0f;
        float m = out[OUT_RPG + idx] * 0.85f + g_rg[idx] / rn;
        out[OUT_RPG + idx] = m;
        out[OUT_RP + idx] -= m * lr;
    } else if (idx < NCAT * NT + NFUNC * NT) {
        int k = idx - NCAT * NT;
        float an = sqrtf(g_norms[0]) + 1.0f;
        float m = out[OUT_AGRE + k] * 0.85f + g_agre[k] / an;
        out[OUT_AGRE + k] = m;
        out[OUT_ARE + k] -= m * lr;
        float m2 = out[OUT_AGIM + k] * 0.85f + g_agim[k] / an;
        out[OUT_AGIM + k] = m2;
        out[OUT_AIM + k] -= m2 * lr;
    } else if (idx < NCAT * NT + NFUNC * NT + NFUNC) {
        int k = idx - NCAT * NT - NFUNC * NT;
        float fn = sqrtf(g_norms[1]) + 1.0f;
        float m = out[OUT_FG + k] * 0.85f + g_fg[k] / fn;
        out[OUT_FG + k] = m;
        out[OUT_FREQ + k] -= m * lr;
    }
}

extern "C" void kernel_launch(void* const* d_in, const int* in_sizes, int n_in,
                              void* d_out, int out_size) {
    const int*   t_p    = (const int*)d_in[0];
    const int*   ds_p   = (const int*)d_in[1];
    const int*   ts     = (const int*)d_in[2];
    const float* x      = (const float*)d_in[3];
    const float* z      = (const float*)d_in[4];
    const float* memory = (const float*)d_in[5];
    const int*   tmem   = (const int*)d_in[6];
    const float* fmem   = (const float*)d_in[7];
    const float* amp_re = (const float*)d_in[8];
    const float* amp_im = (const float*)d_in[9];
    const float* freq   = (const float*)d_in[10];
    const float* cfreq  = (const float*)d_in[11];
    const float* rp     = (const float*)d_in[12];
    const float* fmean  = (const float*)d_in[13];
    const float* bias   = (const float*)d_in[14];
    const float* agre   = (const float*)d_in[15];
    const float* agim   = (const float*)d_in[16];
    const float* fg     = (const float*)d_in[17];
    const float* rpg    = (const float*)d_in[18];
    float* out = (float*)d_out;

    // big verbatim copies into output slots (params are then updated in place)
    cudaMemcpyAsync(out + OUT_MEM,  memory, (size_t)MEMSZ * NT * 4,    cudaMemcpyDeviceToDevice, 0);
    cudaMemcpyAsync(out + OUT_FMEM, fmem,   (size_t)MEMSZ * NFEAT * 4, cudaMemcpyDeviceToDevice, 0);
    cudaMemcpyAsync(out + OUT_ARE,  amp_re, (size_t)NFUNC * NT * 4,    cudaMemcpyDeviceToDevice, 0);
    cudaMemcpyAsync(out + OUT_AIM,  amp_im, (size_t)NFUNC * NT * 4,    cudaMemcpyDeviceToDevice, 0);
    cudaMemcpyAsync(out + OUT_FREQ, freq,   (size_t)NFUNC * 4,         cudaMemcpyDeviceToDevice, 0);
    cudaMemcpyAsync(out + OUT_RP,   rp,     (size_t)NCAT * NT * 4,     cudaMemcpyDeviceToDevice, 0);
    cudaMemcpyAsync(out + OUT_AGRE, agre,   (size_t)NFUNC * NT * 4,    cudaMemcpyDeviceToDevice, 0);
    cudaMemcpyAsync(out + OUT_AGIM, agim,   (size_t)NFUNC * NT * 4,    cudaMemcpyDeviceToDevice, 0);
    cudaMemcpyAsync(out + OUT_FG,   fg,     (size_t)NFUNC * 4,         cudaMemcpyDeviceToDevice, 0);
    cudaMemcpyAsync(out + OUT_RPG,  rpg,    (size_t)NCAT * NT * 4,     cudaMemcpyDeviceToDevice, 0);

    k_prep<<<1, 1024>>>(bias, fmean, z, x, ds_p, out);
    k_tconv<<<(MEMSZ + 255) / 256, 256>>>(tmem, t_p, ds_p, out);
    k_rows<<<1, 1024>>>(z, x, ds_p, out);
    k_gather<<<32, 1024>>>(ts, memory, fmem, tmem, z, x, t_p, ds_p);

    for (int b = 0; b < 2; b++) {
        k_eval<<<16, NT>>>(b, cfreq, out);
        k_r_part<<<dim3(4, 12), 128>>>(b, out);
        k_r_finish<<<16, NT>>>(b);
        k_transpose<<<dim3(16, 16), dim3(32, 32)>>>(out);
        k_backD<<<dim3(4, 16), 128>>>();
        k_ampgrad<<<NFUNC, NT>>>(b, out);
        k_rpgrad<<<NCAT, NT>>>(b);
        k_update<<<((NCAT * NT + NFUNC * NT + NFUNC) + 255) / 256, 256>>>(out);
    }
    (void)in_sizes; (void)n_in; (void)out_size;
}

// round 2
// speedup vs baseline: 1.8767x; 1.8767x over previous
#include <cuda_runtime.h>
#include <math.h>

#define NT 512
#define NFEAT 1024
#define NCAT 1536
#define NFUNC 32
#define MEMSZ 16384
#define SQRTNF 5.656854249492381f

// ---- output layout (float element offsets) ----
#define OUT_MEM    0
#define OUT_TMEM   8388608
#define OUT_FMEM   8404992
#define OUT_ARE    25182208
#define OUT_AIM    25198592
#define OUT_FREQ   25214976
#define OUT_RP     25215008
#define OUT_BIAS   26001440
#define OUT_FMEAN  26001952
#define OUT_AGRE   26002976
#define OUT_AGIM   26019360
#define OUT_FG     26035744
#define OUT_RPG    26035776

// ---- scratch (16B aligned for float4 access) ----
__device__ __align__(16) float g_u[32 * NCAT];
__device__ __align__(16) float g_zb[32 * NT];
__device__ __align__(16) float g_zhat[16 * NT];
__device__ __align__(16) float g_G[16 * NT];
__device__ __align__(16) float g_D[16 * NT];
__device__ __align__(16) float g_ctab[16 * NFUNC];
__device__ __align__(16) float g_stab[16 * NFUNC];
__device__ __align__(16) float g_twopit[32];
__device__ __align__(16) float g_dfrdfq[NFUNC];
__device__ __align__(16) float g_rpart[12 * 16 * NT];
__device__ __align__(16) float g_agre[NFUNC * NT];
__device__ __align__(16) float g_agim[NFUNC * NT];
__device__ __align__(16) float g_fg[NFUNC];
__device__ __align__(16) float g_rg[NCAT * NT];
__device__ float g_norms[3];
__device__ float g_lr;

__device__ __forceinline__ float sgnf(float v) {
    return (v > 0.f) ? 1.f : ((v < 0.f) ? -1.f : 0.f);
}

// ============ side stream: big verbatim copies (no compute deps) ============
__global__ void k_bigcopy(const float* __restrict__ memory, const float* __restrict__ fmem,
                          const int* __restrict__ tmem, float* __restrict__ out) {
    const int N1 = MEMSZ * NT / 4;     // 2097152
    const int N2 = MEMSZ * NFEAT / 4;  // 4194304
    const int N3 = MEMSZ / 4;          // 4096
    long long u = (long long)blockIdx.x * blockDim.x + threadIdx.x;
    if (u < N1) {
        ((float4*)(out + OUT_MEM))[u] = ((const float4*)memory)[u];
    } else if (u < (long long)N1 + N2) {
        int k = (int)(u - N1);
        ((float4*)(out + OUT_FMEM))[k] = ((const float4*)fmem)[k];
    } else if (u < (long long)N1 + N2 + N3) {
        int k = (int)(u - N1 - N2);
        int4 v = ((const int4*)tmem)[k];
        float4 f = make_float4((float)v.x, (float)v.y, (float)v.z, (float)v.w);
        ((float4*)(out + OUT_TMEM))[k] = f;
    }
}

// overwrite updated rows of memory / feat_memory / t_memory in out
__global__ void k_rows(const float* __restrict__ z, const float* __restrict__ x,
                       const int* __restrict__ tp, const int* __restrict__ dsp,
                       float* __restrict__ out) {
    int tid = threadIdx.x;
    int ds = *dsp;
    if (tid < NT)    out[OUT_MEM + ds * NT + tid] = z[tid];
    if (tid < NFEAT) out[OUT_FMEM + ds * NFEAT + tid] = x[tid];
    if (tid == 0)    out[OUT_TMEM + ds] = (float)(*tp);
}

// ============ main stream ============

// param copies + bias/fmean update + lr  (all float4 where possible)
__global__ void k_paramcopy(const float* __restrict__ rp, const float* __restrict__ rpg,
                            const float* __restrict__ are, const float* __restrict__ aim,
                            const float* __restrict__ agre, const float* __restrict__ agim,
                            const float* __restrict__ freq, const float* __restrict__ fg,
                            const float* __restrict__ bias, const float* __restrict__ fmean,
                            const float* __restrict__ z, const float* __restrict__ x,
                            const int* __restrict__ dsp, float* __restrict__ out) {
    const int S_RP = NCAT * NT / 4;   // 196608
    const int S_AMP = NFUNC * NT / 4; // 4096
    int idx = blockIdx.x * blockDim.x + threadIdx.x;
    if (idx == 0) g_lr = (float)pow(0.977, (double)(*dsp + 1));
    int u = idx;
    if (u < S_RP) { ((float4*)(out + OUT_RP))[u] = ((const float4*)rp)[u]; return; }
    u -= S_RP;
    if (u < S_RP) { ((float4*)(out + OUT_RPG))[u] = ((const float4*)rpg)[u]; return; }
    u -= S_RP;
    if (u < S_AMP) { ((float4*)(out + OUT_ARE))[u] = ((const float4*)are)[u]; return; }
    u -= S_AMP;
    if (u < S_AMP) { ((float4*)(out + OUT_AIM))[u] = ((const float4*)aim)[u]; return; }
    u -= S_AMP;
    if (u < S_AMP) { ((float4*)(out + OUT_AGRE))[u] = ((const float4*)agre)[u]; return; }
    u -= S_AMP;
    if (u < S_AMP) { ((float4*)(out + OUT_AGIM))[u] = ((const float4*)agim)[u]; return; }
    u -= S_AMP;
    if (u < 32) { out[OUT_FREQ + u] = freq[u]; return; }
    u -= 32;
    if (u < 32) { out[OUT_FG + u] = fg[u]; return; }
    u -= 32;
    int ds = *dsp;
    float dsn = (float)(ds + 1);
    if (u < NT) { out[OUT_BIAS + u] = (bias[u] * dsn + z[u]) / (dsn + 1.0f); return; }
    u -= NT;
    if (u < NFEAT) { out[OUT_FMEAN + u] = (fmean[u] * dsn + x[u]) / (dsn + 1.0f); return; }
}

// gather all 32 samples (fmean computed inline -> no dependency on paramcopy)
__global__ void k_gather(const int* __restrict__ ts, const float* __restrict__ memory,
                         const float* __restrict__ fmem, const int* __restrict__ tmem,
                         const float* __restrict__ z, const float* __restrict__ x,
                         const float* __restrict__ fmean,
                         const int* __restrict__ tp, const int* __restrict__ dsp) {
    int s = blockIdx.x;
    int tid = threadIdx.x;
    int ds = *dsp;
    float dsn = (float)(ds + 1);
    int idx = ts[s];
    if (tid < NT)
        g_zb[s * NT + tid] = (idx == ds) ? z[tid] : memory[idx * NT + tid];
    float xv = (idx == ds) ? x[tid] : fmem[idx * NFEAT + tid];
    float fm = (fmean[tid] * dsn + x[tid]) / (dsn + 1.0f);
    g_u[s * NCAT + tid] = xv - fm;
    if (tid == 0) {
        float tv = (idx == ds) ? (float)(*tp) : (float)tmem[idx];
        g_twopit[s] = 6.2831853071795864769f * tv;
    }
}

// evaluate z_hat, trig tables, zero norms (bias computed inline from inputs)
__global__ void k_eval(int b, const float* __restrict__ cfreq,
                       const float* __restrict__ bias, const float* __restrict__ z,
                       const int* __restrict__ dsp, float* __restrict__ out) {
    __shared__ float sc[NFUNC], ss[NFUNC];
    int i = blockIdx.x;
    int tid = threadIdx.x;
    float tt = g_twopit[b * 16 + i];
    if (tid < NFUNC) {
        double fq = (double)out[OUT_FREQ + tid];
        double th = tanh(fq);
        double w = (double)cfreq[tid] + 2.0 * th;
        double sg = 1.0 / (1.0 + exp(-w));
        float fr = (float)(sg * 0.5);
        double ph = (double)(tt * fr);
        float cv = (float)cos(ph);
        float sv = (float)sin(ph);
        sc[tid] = cv; ss[tid] = sv;
        g_ctab[i * NFUNC + tid] = cv;
        g_stab[i * NFUNC + tid] = sv;
        if (i == 0)
            g_dfrdfq[tid] = (float)(0.5 * sg * (1.0 - sg) * 2.0 * (1.0 - th * th));
    }
    if (i == 0 && tid >= 64 && tid < 67) g_norms[tid - 64] = 0.f;
    __syncthreads();
    const float* are = out + OUT_ARE;
    const float* aim = out + OUT_AIM;
    float acc = 0.f;
#pragma unroll
    for (int f = 0; f < NFUNC; f++)
        acc += sc[f] * are[f * NT + tid] - ss[f] * aim[f * NT + tid];
    acc /= SQRTNF;
    int ds = *dsp;
    float dsn = (float)(ds + 1);
    float bv = (bias[tid] * dsn + z[tid]) / (dsn + 1.0f);
    g_zhat[i * NT + tid] = acc + bv;
    g_u[(b * 16 + i) * NCAT + NFEAT + tid] = acc;   // z_ - bias == acc
}

// partial r = u @ rp (split over j into 12 slices)
__global__ void k_r_part(int b, const float* __restrict__ out) {
    __shared__ float su[16][128];
    int t = blockIdx.x * 128 + threadIdx.x;
    int j0 = blockIdx.y * 128;
    for (int k = threadIdx.x; k < 16 * 128; k += 128) {
        int i = k >> 7, jj = k & 127;
        su[i][jj] = g_u[(b * 16 + i) * NCAT + j0 + jj];
    }
    __syncthreads();
    const float* rp = out + OUT_RP;
    float acc[16];
#pragma unroll
    for (int i = 0; i < 16; i++) acc[i] = 0.f;
    for (int jj = 0; jj < 128; jj++) {
        float rpv = rp[(j0 + jj) * NT + t];
#pragma unroll
        for (int i = 0; i < 16; i++) acc[i] += su[i][jj] * rpv;
    }
#pragma unroll
    for (int i = 0; i < 16; i++)
        g_rpart[(blockIdx.y * 16 + i) * NT + t] = acc[i];
}

// finish r, compute G and base D
__global__ void k_r_finish(int b) {
    int i = blockIdx.x;
    int t = threadIdx.x;
    int idx = i * NT + t;
    float r = 0.f;
#pragma unroll
    for (int s = 0; s < 12; s++) r += g_rpart[(s * 16 + i) * NT + t];
    float zh = g_zhat[idx];
    float zb = g_zb[(b * 16 + i) * NT + t];
    float ar = fabsf(r) + 1.0f;
    float z2 = zh + r / ar;
    g_G[idx] = (-0.03f / 16.0f) * sgnf(zb - z2) / (ar * ar);
    g_D[idx] = (-1.0f / 16.0f) * sgnf(zb - zh);
}

// D[i][t] += sum_tp G[i][tp] * rp[1024+t][tp]   (transpose-free: both rows contiguous)
__global__ void k_backD(const float* __restrict__ out) {
    __shared__ float srz[NT];
    int t = blockIdx.x;
    const float* rz = out + OUT_RP + (size_t)(NFEAT + t) * NT;
    srz[threadIdx.x] = rz[threadIdx.x];
    srz[threadIdx.x + 256] = rz[threadIdx.x + 256];
    __syncthreads();
    int lane = threadIdx.x & 31;
    int w = threadIdx.x >> 5;   // 0..7
#pragma unroll
    for (int rep = 0; rep < 2; rep++) {
        int i = w + rep * 8;
        float acc = 0.f;
#pragma unroll 4
        for (int tp = lane; tp < NT; tp += 32)
            acc += g_G[i * NT + tp] * srz[tp];
#pragma unroll
        for (int o = 16; o > 0; o >>= 1)
            acc += __shfl_down_sync(0xffffffffu, acc, o);
        if (lane == 0) g_D[i * NT + t] += acc;
    }
}

// fused amp/freq gradients (blocks 0..31) + rp gradient (blocks 32..1567)
__global__ void k_grads(int b, const float* __restrict__ out) {
    __shared__ float sh[NT];
    int t = threadIdx.x;
    if (blockIdx.x < 32) {
        int f = blockIdx.x;
        float are = out[OUT_ARE + f * NT + t];
        float aim = out[OUT_AIM + f * NT + t];
        float sre = 0.f, sim = 0.f, sf = 0.f;
#pragma unroll
        for (int i = 0; i < 16; i++) {
            float d = g_D[i * NT + t];
            float c = g_ctab[i * NFUNC + f];
            float s = g_stab[i * NFUNC + f];
            sre += d * c;
            sim -= d * s;
            sf += d * (-s * are - c * aim) * g_twopit[b * 16 + i];
        }
        float q = are * are + aim * aim;
        float aa = sqrtf(q);
        float reg = 0.01f / (2.0f * aa * sqrtf(aa));
        float agre = sre / SQRTNF + are * reg;
        float agim = sim / SQRTNF + aim * reg;
        g_agre[f * NT + t] = agre;
        g_agim[f * NT + t] = agim;

        sh[t] = sf;
        __syncthreads();
        for (int s2 = 256; s2 > 0; s2 >>= 1) {
            if (t < s2) sh[t] += sh[t + s2];
            __syncthreads();
        }
        if (t == 0) {
            float fg = (sh[0] / SQRTNF) * g_dfrdfq[f];
            g_fg[f] = fg;
            atomicAdd(&g_norms[1], fg * fg);
        }
        __syncthreads();
        sh[t] = agre * agre + agim * agim;
        __syncthreads();
        for (int s2 = 256; s2 > 0; s2 >>= 1) {
            if (t < s2) sh[t] += sh[t + s2];
            __syncthreads();
        }
        if (t == 0) atomicAdd(&g_norms[0], sh[0]);
    } else {
        int j = blockIdx.x - 32;
        float acc = 0.f;
#pragma unroll
        for (int i = 0; i < 16; i++)
            acc += g_u[(b * 16 + i) * NCAT + j] * g_G[i * NT + t];
        g_rg[j * NT + t] = acc;
        sh[t] = acc * acc;
        __syncthreads();
        for (int s = 256; s > 0; s >>= 1) {
            if (t < s) sh[t] += sh[t + s];
            __syncthreads();
        }
        if (t == 0) atomicAdd(&g_norms[2], sh[0]);
    }
}

// momentum updates, float4-vectorized, in place in d_out
__global__ void k_update(float* __restrict__ out) {
    const int NRP4 = NCAT * NT / 4;   // 196608
    const int NAMP4 = NFUNC * NT / 4; // 4096
    int idx = blockIdx.x * blockDim.x + threadIdx.x;
    float lr = g_lr;
    if (idx < NRP4) {
        float rn = sqrtf(g_norms[2]) + 1.0f;
        float4 mo = ((float4*)(out + OUT_RPG))[idx];
        float4 gr = ((const float4*)g_rg)[idx];
        float4 pv = ((float4*)(out + OUT_RP))[idx];
        mo.x = mo.x * 0.85f + gr.x / rn;  pv.x -= mo.x * lr;
        mo.y = mo.y * 0.85f + gr.y / rn;  pv.y -= mo.y * lr;
        mo.z = mo.z * 0.85f + gr.z / rn;  pv.z -= mo.z * lr;
        mo.w = mo.w * 0.85f + gr.w / rn;  pv.w -= mo.w * lr;
        ((float4*)(out + OUT_RPG))[idx] = mo;
        ((float4*)(out + OUT_RP))[idx] = pv;
    } else if (idx < NRP4 + NAMP4) {
        int k = idx - NRP4;
        float an = sqrtf(g_norms[0]) + 1.0f;
        float4 mo = ((float4*)(out + OUT_AGRE))[k];
        float4 gr = ((const float4*)g_agre)[k];
        float4 pv = ((float4*)(out + OUT_ARE))[k];
        mo.x = mo.x * 0.85f + gr.x / an;  pv.x -= mo.x * lr;
        mo.y = mo.y * 0.85f + gr.y / an;  pv.y -= mo.y * lr;
        mo.z = mo.z * 0.85f + gr.z / an;  pv.z -= mo.z * lr;
        mo.w = mo.w * 0.85f + gr.w / an;  pv.w -= mo.w * lr;
        ((float4*)(out + OUT_AGRE))[k] = mo;
        ((float4*)(out + OUT_ARE))[k] = pv;
        float4 mi = ((float4*)(out + OUT_AGIM))[k];
        float4 gi = ((const float4*)g_agim)[k];
        float4 pi = ((float4*)(out + OUT_AIM))[k];
        mi.x = mi.x * 0.85f + gi.x / an;  pi.x -= mi.x * lr;
        mi.y = mi.y * 0.85f + gi.y / an;  pi.y -= mi.y * lr;
        mi.z = mi.z * 0.85f + gi.z / an;  pi.z -= mi.z * lr;
        mi.w = mi.w * 0.85f + gi.w / an;  pi.w -= mi.w * lr;
        ((float4*)(out + OUT_AGIM))[k] = mi;
        ((float4*)(out + OUT_AIM))[k] = pi;
    } else if (idx < NRP4 + NAMP4 + 32) {
        int k = idx - NRP4 - NAMP4;
        float fn = sqrtf(g_norms[1]) + 1.0f;
        float m = out[OUT_FG + k] * 0.85f + g_fg[k] / fn;
        out[OUT_FG + k] = m;
        out[OUT_FREQ + k] -= m * lr;
    }
}

extern "C" void kernel_launch(void* const* d_in, const int* in_sizes, int n_in,
                              void* d_out, int out_size) {
    const int*   t_p    = (const int*)d_in[0];
    const int*   ds_p   = (const int*)d_in[1];
    const int*   ts     = (const int*)d_in[2];
    const float* x      = (const float*)d_in[3];
    const float* z      = (const float*)d_in[4];
    const float* memory = (const float*)d_in[5];
    const int*   tmem   = (const int*)d_in[6];
    const float* fmem   = (const float*)d_in[7];
    const float* amp_re = (const float*)d_in[8];
    const float* amp_im = (const float*)d_in[9];
    const float* freq   = (const float*)d_in[10];
    const float* cfreq  = (const float*)d_in[11];
    const float* rp     = (const float*)d_in[12];
    const float* fmean  = (const float*)d_in[13];
    const float* bias   = (const float*)d_in[14];
    const float* agre   = (const float*)d_in[15];
    const float* agim   = (const float*)d_in[16];
    const float* fg     = (const float*)d_in[17];
    const float* rpg    = (const float*)d_in[18];
    float* out = (float*)d_out;

    // lazy side-stream + events (created on first, uncaptured, correctness call)
    static cudaStream_t s1 = 0;
    static cudaEvent_t e0 = 0, e1 = 0;
    if (!s1) {
        cudaStreamCreateWithFlags(&s1, cudaStreamNonBlocking);
        cudaEventCreateWithFlags(&e0, cudaEventDisableTiming);
        cudaEventCreateWithFlags(&e1, cudaEventDisableTiming);
    }

    // ---- fork: big copies run concurrently with the optimizer chain ----
    cudaEventRecord(e0, 0);
    cudaStreamWaitEvent(s1, e0, 0);
    {
        const long long total4 = (long long)MEMSZ * NT / 4 + (long long)MEMSZ * NFEAT / 4 + MEMSZ / 4;
        int blocks = (int)((total4 + 255) / 256);
        k_bigcopy<<<blocks, 256, 0, s1>>>(memory, fmem, tmem, out);
        k_rows<<<1, 1024, 0, s1>>>(z, x, t_p, ds_p, out);
    }
    cudaEventRecord(e1, s1);

    // ---- main chain ----
    {
        const int total = NCAT * NT / 4 * 2 + NFUNC * NT / 4 * 4 + 64 + NT + NFEAT;
        k_paramcopy<<<(total + 255) / 256, 256>>>(rp, rpg, amp_re, amp_im, agre, agim,
                                                  freq, fg, bias, fmean, z, x, ds_p, out);
    }
    k_gather<<<32, 1024>>>(ts, memory, fmem, tmem, z, x, fmean, t_p, ds_p);

    for (int b = 0; b < 2; b++) {
        k_eval<<<16, NT>>>(b, cfreq, bias, z, ds_p, out);
        k_r_part<<<dim3(4, 12), 128>>>(b, out);
        k_r_finish<<<16, NT>>>(b);
        k_backD<<<NT, 256>>>(out);
        k_grads<<<32 + NCAT, NT>>>(b, out);
        k_update<<<(NCAT * NT / 4 + NFUNC * NT / 4 + 32 + 255) / 256, 256>>>(out);
    }

    // ---- join ----
    cudaStreamWaitEvent(0, e1, 0);
    (void)in_sizes; (void)n_in; (void)out_size;
}

// round 4
// speedup vs baseline: 2.8574x; 1.5226x over previous
#include <cuda_runtime.h>
#include <math.h>

#define NT 512
#define NFEAT 1024
#define NCAT 1536
#define NFUNC 32
#define MEMSZ 16384
#define RSQRTNF 0.17677669529663689f

// ---- output layout (float element offsets) ----
#define OUT_MEM    0
#define OUT_TMEM   8388608
#define OUT_FMEM   8404992
#define OUT_ARE    25182208
#define OUT_AIM    25198592
#define OUT_FREQ   25214976
#define OUT_RP     25215008
#define OUT_BIAS   26001440
#define OUT_FMEAN  26001952
#define OUT_AGRE   26002976
#define OUT_AGIM   26019360
#define OUT_FG     26035744
#define OUT_RPG    26035776

// ---- scratch ----
__device__ __align__(16) float g_u[32 * NCAT];
__device__ __align__(16) float g_zb[32 * NT];
__device__ __align__(16) float g_G[16 * NT];
__device__ __align__(16) float g_D[16 * NT];
__device__ __align__(16) float g_ctab[16 * NFUNC];
__device__ __align__(16) float g_stab[16 * NFUNC];
__device__ __align__(16) float g_twopit[32];
__device__ __align__(16) float g_dfrdfq[NFUNC];
__device__ __align__(16) float g_agre[NFUNC * NT];
__device__ __align__(16) float g_agim[NFUNC * NT];
__device__ __align__(16) float g_fgacc[NFUNC];
__device__ __align__(16) float g_rg[NCAT * NT];
__device__ float g_norms[3];   // [0]=amp sumsq, [2]=rp sumsq
__device__ float g_lr;

__device__ __forceinline__ float sgnf(float v) {
    return (v > 0.f) ? 1.f : ((v < 0.f) ? -1.f : 0.f);
}

// ================= side stream: big copies with inline row substitution =================
__global__ void k_bigcopy(const float* __restrict__ memory, const float* __restrict__ fmem,
                          const int* __restrict__ tmem,
                          const float* __restrict__ z, const float* __restrict__ x,
                          const int* __restrict__ tp, const int* __restrict__ dsp,
                          float* __restrict__ out) {
    const long long N1 = (long long)MEMSZ * NT / 4;     // 2097152
    const long long N2c = (long long)MEMSZ * NFEAT / 4; // 4194304
    const long long N3c = MEMSZ / 4;                    // 4096
    long long u = (long long)blockIdx.x * 256 + threadIdx.x;
    int ds = *dsp;
    if (u < N1) {
        int k = (int)u;
        int gf = k * 4;
        int row = gf >> 9;
        float4 v;
        if (row == ds) v = *(const float4*)(z + (gf & 511));
        else           v = ((const float4*)memory)[k];
        ((float4*)(out + OUT_MEM))[k] = v;
    } else if (u < N1 + N2c) {
        int k = (int)(u - N1);
        int gf = k * 4;
        int row = gf >> 10;
        float4 v;
        if (row == ds) v = *(const float4*)(x + (gf & 1023));
        else           v = ((const float4*)fmem)[k];
        ((float4*)(out + OUT_FMEM))[k] = v;
    } else if (u < N1 + N2c + N3c) {
        int k = (int)(u - N1 - N2c);
        int4 iv = ((const int4*)tmem)[k];
        float4 f = make_float4((float)iv.x, (float)iv.y, (float)iv.z, (float)iv.w);
        if ((ds >> 2) == k) ((float*)&f)[ds & 3] = (float)(*tp);
        ((float4*)(out + OUT_TMEM))[k] = f;
    }
}

// ================= front: gather (32 samples) + batch-0 eval + param copies =================
__global__ void k_front(const int* __restrict__ ts, const float* __restrict__ memory,
                        const float* __restrict__ fmem, const int* __restrict__ tmem,
                        const float* __restrict__ z, const float* __restrict__ x,
                        const float* __restrict__ fmean, const float* __restrict__ bias,
                        const int* __restrict__ tp, const int* __restrict__ dsp,
                        const float* __restrict__ freq_in, const float* __restrict__ cf,
                        const float* __restrict__ are_in, const float* __restrict__ aim_in,
                        const float* __restrict__ rp, const float* __restrict__ rpg,
                        const float* __restrict__ agre_in, const float* __restrict__ agim_in,
                        const float* __restrict__ fg_in, float* __restrict__ out) {
    int bid = blockIdx.x, tid = threadIdx.x;  // 512 threads
    if (bid < 32) {
        __shared__ float sc[NFUNC], ss[NFUNC], stt;
        int s = bid;
        int ds = *dsp;
        float dsn = (float)(ds + 1);
        int idx = ts[s];
        g_zb[s * NT + tid] = (idx == ds) ? z[tid] : memory[idx * NT + tid];
        for (int jj = tid; jj < NFEAT; jj += 512) {
            float xv = (idx == ds) ? x[jj] : fmem[idx * NFEAT + jj];
            float fm = (fmean[jj] * dsn + x[jj]) / (dsn + 1.0f);
            g_u[s * NCAT + jj] = xv - fm;
        }
        if (tid == 0) {
            float tv = (idx == ds) ? (float)(*tp) : (float)tmem[idx];
            float tt = 6.2831853071795864769f * tv;
            g_twopit[s] = tt;
            stt = tt;
        }
        if (s < 16) {
            __syncthreads();
            if (tid < NFUNC) {
                double fq = (double)freq_in[tid];
                double th = tanh(fq);
                double w = (double)cf[tid] + 2.0 * th;
                double sg = 1.0 / (1.0 + exp(-w));
                double ph = (double)stt * (sg * 0.5);
                float cv = (float)cos(ph);
                float sv = (float)sin(ph);
                sc[tid] = cv; ss[tid] = sv;
                g_ctab[s * NFUNC + tid] = cv;
                g_stab[s * NFUNC + tid] = sv;
                if (s == 0)
                    g_dfrdfq[tid] = (float)(0.5 * sg * (1.0 - sg) * 2.0 * (1.0 - th * th));
            }
            __syncthreads();
            float acc = 0.f;
#pragma unroll
            for (int f = 0; f < NFUNC; f++)
                acc += sc[f] * are_in[f * NT + tid] - ss[f] * aim_in[f * NT + tid];
            g_u[s * NCAT + NFEAT + tid] = acc * RSQRTNF;
        }
    } else {
        // param copies + bias/fmean + lr
        const int S_RP = NCAT * NT / 4;
        const int S_AMP = NFUNC * NT / 4;
        int u = (bid - 32) * 512 + tid;
        if (u == 0) g_lr = (float)pow(0.977, (double)(*dsp + 1));
        if (u < S_RP) { ((float4*)(out + OUT_RP))[u] = ((const float4*)rp)[u]; return; }
        u -= S_RP;
        if (u < S_RP) { ((float4*)(out + OUT_RPG))[u] = ((const float4*)rpg)[u]; return; }
        u -= S_RP;
        if (u < S_AMP) { ((float4*)(out + OUT_ARE))[u] = ((const float4*)are_in)[u]; return; }
        u -= S_AMP;
        if (u < S_AMP) { ((float4*)(out + OUT_AIM))[u] = ((const float4*)aim_in)[u]; return; }
        u -= S_AMP;
        if (u < S_AMP) { ((float4*)(out + OUT_AGRE))[u] = ((const float4*)agre_in)[u]; return; }
        u -= S_AMP;
        if (u < S_AMP) { ((float4*)(out + OUT_AGIM))[u] = ((const float4*)agim_in)[u]; return; }
        u -= S_AMP;
        if (u < 32) { out[OUT_FREQ + u] = freq_in[u]; return; }
        u -= 32;
        if (u < 32) { out[OUT_FG + u] = fg_in[u]; return; }
        u -= 32;
        int ds = *dsp;
        float dsn = (float)(ds + 1);
        if (u < NT) { out[OUT_BIAS + u] = (bias[u] * dsn + z[u]) / (dsn + 1.0f); return; }
        u -= NT;
        if (u < NFEAT) { out[OUT_FMEAN + u] = (fmean[u] * dsn + x[u]) / (dsn + 1.0f); return; }
    }
}

// ================= N2: [optional eval] + full r + G + D-base =================
// grid 64 = (i 0..15) x (t-quarter 0..3), 256 threads
__global__ void k_N2(int b, int do_eval,
                     const float* __restrict__ freq_p, const float* __restrict__ cf,
                     const float* __restrict__ are_p, const float* __restrict__ aim_p,
                     const float* __restrict__ rp_p,
                     const float* __restrict__ bias_p, const float* __restrict__ z_p,
                     const int* __restrict__ dsp) {
    __shared__ float smu[NCAT];
    __shared__ float red[8][32][4];
    __shared__ float sc[NFUNC], ss[NFUNC];
    int tid = threadIdx.x;
    int i = blockIdx.x >> 2, tq = blockIdx.x & 3;
    if (blockIdx.x == 0) {
        if (tid < 3) g_norms[tid] = 0.f;
        if (tid >= 32 && tid < 64) g_fgacc[tid - 32] = 0.f;
    }
    for (int k = tid; k < NFEAT; k += 256)
        smu[k] = g_u[(b * 16 + i) * NCAT + k];
    if (do_eval) {
        if (tid < NFUNC) {
            double fq = (double)freq_p[tid];
            double th = tanh(fq);
            double w = (double)cf[tid] + 2.0 * th;
            double sg = 1.0 / (1.0 + exp(-w));
            double ph = (double)g_twopit[b * 16 + i] * (sg * 0.5);
            float cv = (float)cos(ph);
            float sv = (float)sin(ph);
            sc[tid] = cv; ss[tid] = sv;
            if (tq == 0) {
                g_ctab[i * NFUNC + tid] = cv;
                g_stab[i * NFUNC + tid] = sv;
            }
            if (blockIdx.x == 0)
                g_dfrdfq[tid] = (float)(0.5 * sg * (1.0 - sg) * 2.0 * (1.0 - th * th));
        }
        __syncthreads();
        for (int t2 = tid; t2 < NT; t2 += 256) {
            float acc = 0.f;
#pragma unroll
            for (int f = 0; f < NFUNC; f++)
                acc += sc[f] * are_p[f * NT + t2] - ss[f] * aim_p[f * NT + t2];
            acc *= RSQRTNF;
            smu[NFEAT + t2] = acc;
            if (tq == 0) g_u[(b * 16 + i) * NCAT + NFEAT + t2] = acc;
        }
    } else {
        for (int t2 = tid; t2 < NT; t2 += 256)
            smu[NFEAT + t2] = g_u[(b * 16 + i) * NCAT + NFEAT + t2];
    }
    __syncthreads();
    // r: thread = (t-quad q, j-slice js)
    int q = tid & 31, js = tid >> 5;
    int tb = tq * 128 + q * 4;
    float a0 = 0.f, a1 = 0.f, a2 = 0.f, a3 = 0.f;
    const float* rpb = rp_p + tb;
    int j0 = js * 192;
#pragma unroll 8
    for (int j = j0; j < j0 + 192; j++) {
        float uv = smu[j];
        float4 rv = *(const float4*)(rpb + (size_t)j * NT);
        a0 += uv * rv.x; a1 += uv * rv.y; a2 += uv * rv.z; a3 += uv * rv.w;
    }
    red[js][q][0] = a0; red[js][q][1] = a1; red[js][q][2] = a2; red[js][q][3] = a3;
    __syncthreads();
    if (tid < 128) {
        int qq = tid >> 2, c = tid & 3;
        float rt = 0.f;
#pragma unroll
        for (int k = 0; k < 8; k++) rt += red[k][qq][c];
        int t = tq * 128 + qq * 4 + c;
        int ds = *dsp;
        float dsn = (float)(ds + 1);
        float bv = (bias_p[t] * dsn + z_p[t]) / (dsn + 1.0f);
        float zh = smu[NFEAT + t] + bv;
        float zb = g_zb[(b * 16 + i) * NT + t];
        float ar = fabsf(rt) + 1.0f;
        float z2 = zh + rt / ar;
        g_G[i * NT + t] = (-0.03f / 16.0f) * sgnf(zb - z2) / (ar * ar);
        g_D[i * NT + t] = (-1.0f / 16.0f) * sgnf(zb - zh);
    }
}

// ================= N3: backD+ampgrad (blocks 0..511) | rg (blocks 512..895) =================
// 512 threads per block in BOTH branches.
__global__ void k_N3(int b, const float* __restrict__ rp_p,
                     const float* __restrict__ are_p, const float* __restrict__ aim_p) {
    if (blockIdx.x < 512) {
        __shared__ float srz[NT];
        __shared__ float sD[16];
        __shared__ float stt[16];
        int t = blockIdx.x, tid = threadIdx.x;  // 512 threads
        srz[tid] = rp_p[(size_t)(NFEAT + t) * NT + tid];
        if (tid < 16) stt[tid] = g_twopit[b * 16 + tid];
        __syncthreads();
        int lane = tid & 31, w = tid >> 5;   // w = 0..15 = sample i
        float acc = 0.f;
#pragma unroll 4
        for (int tp = lane; tp < NT; tp += 32)
            acc += g_G[w * NT + tp] * srz[tp];
#pragma unroll
        for (int o = 16; o > 0; o >>= 1)
            acc += __shfl_down_sync(0xffffffffu, acc, o);
        if (lane == 0) sD[w] = g_D[w * NT + t] + acc;
        __syncthreads();
        if (tid < NFUNC) {
            int f = tid;
            float are = are_p[f * NT + t], aim = aim_p[f * NT + t];
            float sre = 0.f, sim = 0.f, sf = 0.f;
#pragma unroll
            for (int i = 0; i < 16; i++) {
                float d = sD[i];
                float c = g_ctab[i * NFUNC + f];
                float s = g_stab[i * NFUNC + f];
                sre += d * c;
                sim -= d * s;
                sf += d * (-s * are - c * aim) * stt[i];
            }
            float aa = sqrtf(are * are + aim * aim);
            float reg = 0.01f / (2.0f * aa * sqrtf(aa));
            float agre = sre * RSQRTNF + are * reg;
            float agim = sim * RSQRTNF + aim * reg;
            g_agre[f * NT + t] = agre;
            g_agim[f * NT + t] = agim;
            atomicAdd(&g_fgacc[f], sf);
            float nrm = agre * agre + agim * agim;
#pragma unroll
            for (int o = 16; o > 0; o >>= 1)
                nrm += __shfl_down_sync(0xffffffffu, nrm, o);
            if (f == 0) atomicAdd(&g_norms[0], nrm);
        }
    } else {
        __shared__ float su[16][4];
        __shared__ float swr[16];
        int j0 = (blockIdx.x - 512) * 4, tid = threadIdx.x;  // 512 threads
        if (tid < 64)
            su[tid >> 2][tid & 3] = g_u[(b * 16 + (tid >> 2)) * NCAT + j0 + (tid & 3)];
        __syncthreads();
        float a[4] = {0.f, 0.f, 0.f, 0.f};
#pragma unroll
        for (int i = 0; i < 16; i++) {
            float gv = g_G[i * NT + tid];
            a[0] += su[i][0] * gv; a[1] += su[i][1] * gv;
            a[2] += su[i][2] * gv; a[3] += su[i][3] * gv;
        }
        float loc = 0.f;
#pragma unroll
        for (int jj = 0; jj < 4; jj++) {
            g_rg[(j0 + jj) * NT + tid] = a[jj];
            loc += a[jj] * a[jj];
        }
#pragma unroll
        for (int o = 16; o > 0; o >>= 1)
            loc += __shfl_down_sync(0xffffffffu, loc, o);
        if ((tid & 31) == 0) swr[tid >> 5] = loc;
        __syncthreads();
        if (tid < 16) {
            loc = swr[tid];
#pragma unroll
            for (int o = 8; o > 0; o >>= 1)
                loc += __shfl_down_sync(0x0000ffffu, loc, o);
            if (tid == 0) atomicAdd(&g_norms[2], loc);
        }
    }
}

// ================= update =================
__global__ void k_update(float* __restrict__ out) {
    const int NRP4 = NCAT * NT / 4;
    const int NAMP4 = NFUNC * NT / 4;
    int idx = blockIdx.x * 256 + threadIdx.x;
    float lr = g_lr;
    if (idx < NRP4) {
        float rn = sqrtf(g_norms[2]) + 1.0f;
        float4 mo = ((float4*)(out + OUT_RPG))[idx];
        float4 gr = ((const float4*)g_rg)[idx];
        float4 pv = ((float4*)(out + OUT_RP))[idx];
        mo.x = mo.x * 0.85f + gr.x / rn;  pv.x -= mo.x * lr;
        mo.y = mo.y * 0.85f + gr.y / rn;  pv.y -= mo.y * lr;
        mo.z = mo.z * 0.85f + gr.z / rn;  pv.z -= mo.z * lr;
        mo.w = mo.w * 0.85f + gr.w / rn;  pv.w -= mo.w * lr;
        ((float4*)(out + OUT_RPG))[idx] = mo;
        ((float4*)(out + OUT_RP))[idx] = pv;
    } else if (idx < NRP4 + NAMP4) {
        int k = idx - NRP4;
        float an = sqrtf(g_norms[0]) + 1.0f;
        float4 mo = ((float4*)(out + OUT_AGRE))[k];
        float4 gr = ((const float4*)g_agre)[k];
        float4 pv = ((float4*)(out + OUT_ARE))[k];
        mo.x = mo.x * 0.85f + gr.x / an;  pv.x -= mo.x * lr;
        mo.y = mo.y * 0.85f + gr.y / an;  pv.y -= mo.y * lr;
        mo.z = mo.z * 0.85f + gr.z / an;  pv.z -= mo.z * lr;
        mo.w = mo.w * 0.85f + gr.w / an;  pv.w -= mo.w * lr;
        ((float4*)(out + OUT_AGRE))[k] = mo;
        ((float4*)(out + OUT_ARE))[k] = pv;
        float4 mi = ((float4*)(out + OUT_AGIM))[k];
        float4 gi = ((const float4*)g_agim)[k];
        float4 pi = ((float4*)(out + OUT_AIM))[k];
        mi.x = mi.x * 0.85f + gi.x / an;  pi.x -= mi.x * lr;
        mi.y = mi.y * 0.85f + gi.y / an;  pi.y -= mi.y * lr;
        mi.z = mi.z * 0.85f + gi.z / an;  pi.z -= mi.z * lr;
        mi.w = mi.w * 0.85f + gi.w / an;  pi.w -= mi.w * lr;
        ((float4*)(out + OUT_AGIM))[k] = mi;
        ((float4*)(out + OUT_AIM))[k] = pi;
    }
    // freq update: one warp, finalizes fg and its norm
    if (blockIdx.x == 0 && threadIdx.x < 32) {
        int f = threadIdx.x;
        float fgv = (g_fgacc[f] * RSQRTNF) * g_dfrdfq[f];
        float n = fgv * fgv;
#pragma unroll
        for (int o = 16; o > 0; o >>= 1)
            n += __shfl_xor_sync(0xffffffffu, n, o);
        float fn = sqrtf(n) + 1.0f;
        float m = out[OUT_FG + f] * 0.85f + fgv / fn;
        out[OUT_FG + f] = m;
        out[OUT_FREQ + f] -= m * lr;
    }
}

extern "C" void kernel_launch(void* const* d_in, const int* in_sizes, int n_in,
                              void* d_out, int out_size) {
    const int*   t_p    = (const int*)d_in[0];
    const int*   ds_p   = (const int*)d_in[1];
    const int*   ts     = (const int*)d_in[2];
    const float* x      = (const float*)d_in[3];
    const float* z      = (const float*)d_in[4];
    const float* memory = (const float*)d_in[5];
    const int*   tmem   = (const int*)d_in[6];
    const float* fmem   = (const float*)d_in[7];
    const float* amp_re = (const float*)d_in[8];
    const float* amp_im = (const float*)d_in[9];
    const float* freq   = (const float*)d_in[10];
    const float* cfreq  = (const float*)d_in[11];
    const float* rp     = (const float*)d_in[12];
    const float* fmean  = (const float*)d_in[13];
    const float* bias   = (const float*)d_in[14];
    const float* agre   = (const float*)d_in[15];
    const float* agim   = (const float*)d_in[16];
    const float* fg     = (const float*)d_in[17];
    const float* rpg    = (const float*)d_in[18];
    float* out = (float*)d_out;

    static cudaStream_t s1 = 0;
    static cudaEvent_t e0 = 0, e1 = 0;
    if (!s1) {
        cudaStreamCreateWithFlags(&s1, cudaStreamNonBlocking);
        cudaEventCreateWithFlags(&e0, cudaEventDisableTiming);
        cudaEventCreateWithFlags(&e1, cudaEventDisableTiming);
    }

    // ---- fork: one big copy kernel on side stream ----
    cudaEventRecord(e0, 0);
    cudaStreamWaitEvent(s1, e0, 0);
    {
        const long long total4 = (long long)MEMSZ * NT / 4 + (long long)MEMSZ * NFEAT / 4 + MEMSZ / 4;
        int blocks = (int)((total4 + 255) / 256);
        k_bigcopy<<<blocks, 256, 0, s1>>>(memory, fmem, tmem, z, x, t_p, ds_p, out);
    }
    cudaEventRecord(e1, s1);

    // ---- main chain: 7 nodes ----
    {
        const int PCU = NCAT * NT / 4 * 2 + NFUNC * NT / 4 * 4 + 64 + NT + NFEAT; // 411200
        int pc_blocks = (PCU + 511) / 512;  // 804
        k_front<<<32 + pc_blocks, 512>>>(ts, memory, fmem, tmem, z, x, fmean, bias,
                                         t_p, ds_p, freq, cfreq, amp_re, amp_im,
                                         rp, rpg, agre, agim, fg, out);
    }

    // batch 0: params from inputs
    k_N2<<<64, 256>>>(0, 0, freq, cfreq, amp_re, amp_im, rp, bias, z, ds_p);
    k_N3<<<512 + NCAT / 4, 512>>>(0, rp, amp_re, amp_im);
    k_update<<<(NCAT * NT / 4 + NFUNC * NT / 4) / 256, 256>>>(out);

    // batch 1: params from out (updated)
    k_N2<<<64, 256>>>(1, 1, out + OUT_FREQ, cfreq, out + OUT_ARE, out + OUT_AIM,
                      out + OUT_RP, bias, z, ds_p);
    k_N3<<<512 + NCAT / 4, 512>>>(1, out + OUT_RP, out + OUT_ARE, out + OUT_AIM);
    k_update<<<(NCAT * NT / 4 + NFUNC * NT / 4) / 256, 256>>>(out);

    // ---- join ----
    cudaStreamWaitEvent(0, e1, 0);
    (void)in_sizes; (void)n_in; (void)out_size;
}